// round 15
// baseline (speedup 1.0000x reference)
#include <cuda_runtime.h>
#include <math.h>

// ---------------------------------------------------------------------------
// GaussianRasterizer — memset + prepass + fine-grained raster.
//   gr_prep  : per Gaussian: bbox vector {mx,my,ex,ey} (tile half folded) +
//              eval-ready {mx,my,qa,qb2}/{qc, o*c} with -0.5*log2e folded.
//   gr_raster: grid (tilesX, tilesY, NSEG). Each 128-thread CTA rasterizes
//              one 16x8 tile against one N/NSEG segment and composites its
//              partial into out via atomicAdd (REDG). Fine granularity =>
//              hardware load-balances the unequal tiles.
// Float atomic reordering across segments perturbs ~1e-7 rel (gate: 1e-3).
// ---------------------------------------------------------------------------

#define TILE_W 16
#define TILE_H 8
#define NT 128
#define NSEG 4
#define CPT 4
#define CHUNK (NT * CPT)        // 512 candidates per chunk
#define CAP 256                 // survivor batch capacity
#define MAXN 8192

__device__ float4 g_bb[MAXN];   // {mx, my, ex, ey} (ex,ey include tile half)
__device__ float4 g_p0[MAXN];   // {mx, my, qa, qb2}
__device__ float4 g_p1[MAXN];   // {qc, o*cr, o*cg, o*cb}

__device__ __forceinline__ float scalar_as_float(const int* p) {
    int v = *p;
    if (v >= 0 && v <= 1000000) return (float)v;
    return __int_as_float(v);
}

__device__ __forceinline__ float ex2(float q) {
    float r;
    asm("ex2.approx.ftz.f32 %0, %1;" : "=f"(r) : "f"(q));
    return r;
}

__global__ __launch_bounds__(256)
void gr_prep(const float* __restrict__ opacity,
             const float* __restrict__ means,
             const float* __restrict__ stds,
             const float* __restrict__ rhos,
             const float* __restrict__ colors,
             const int*   __restrict__ scale_p,
             const int*   __restrict__ ratio_p,
             int N) {
    const int i = blockIdx.x * blockDim.x + threadIdx.x;
    if (i >= N) return;

    const float s    = scalar_as_float(scale_p);
    const float r    = scalar_as_float(ratio_p);
    const float rs   = r * s;
    const float HL2E = -0.5f * 1.44269504088896340736f;   // -0.5*log2(e)

    float2 mn = ((const float2*)means)[i];
    float2 st = ((const float2*)stds)[i];
    float rho = rhos[i];
    float o   = opacity[i];
    float c0  = colors[3 * i + 0];
    float c1  = colors[3 * i + 1];
    float c2  = colors[3 * i + 2];

    float sx = st.x * s;
    float sy = st.y * s;
    float om = 1.0f - rho * rho;
    float qa  = __fdividef(HL2E,               sx * sx * om);
    float qc  = __fdividef(HL2E,               sy * sy * om);
    float qb2 = __fdividef(-2.0f * HL2E * rho, sx * sy * om);

    g_bb[i] = make_float4(mn.x, mn.y,
                          fmaf(rs, st.x, (TILE_W - 1) * 0.5f),
                          fmaf(rs, st.y, (TILE_H - 1) * 0.5f));
    g_p0[i] = make_float4(mn.x, mn.y, qa, qb2);
    g_p1[i] = make_float4(qc, o * c0, o * c1, o * c2);
}

__global__ __launch_bounds__(NT)
void gr_raster(const int* __restrict__ ratio_p,
               float* __restrict__ out, int N, int W, int H) {
    __shared__ float4 s0[CAP];
    __shared__ float4 s1[CAP];
    __shared__ int    swc[NT / 32];

    const int tid  = threadIdx.x;
    const int lane = tid & 31;
    const int wid  = tid >> 5;

    const int px = blockIdx.x * TILE_W + (tid & (TILE_W - 1));
    const int py = blockIdx.y * TILE_H + (tid / TILE_W);
    const float x = (float)px + 0.5f;
    const float y = (float)py + 0.5f;

    const float tcx = (float)(blockIdx.x * TILE_W) + 0.5f + (TILE_W - 1) * 0.5f;
    const float tcy = (float)(blockIdx.y * TILE_H) + 0.5f + (TILE_H - 1) * 0.5f;

    const float r    = scalar_as_float(ratio_p);
    const float HL2E = -0.5f * 1.44269504088896340736f;
    const float cth  = HL2E * r * r;      // pass when folded q >= cth

    // This CTA's segment.
    const int segN = (N + NSEG - 1) / NSEG;
    const int beg  = blockIdx.z * segN;
    const int end  = min(N, beg + segN);

    float ar0 = 0.f, ag0 = 0.f, ab0 = 0.f;
    float ar1 = 0.f, ag1 = 0.f, ab1 = 0.f;

    for (int base = beg; base < end; base += CHUNK) {
        // ---- Cull: CPT candidates per thread, 1 LDG.128 each.
        const int ib = base + tid * CPT;
        unsigned hm = 0;
        #pragma unroll
        for (int k = 0; k < CPT; k++) {
            int i = ib + k;
            if (i < end) {
                float4 bb = g_bb[i];
                bool hit = (fabsf(bb.x - tcx) <= bb.z) &
                           (fabsf(bb.y - tcy) <= bb.w);
                if (hit) hm |= (1u << k);
            }
        }
        int cnt = __popc(hm);

        // ---- 3-ballot prefix scan (cnt in 0..4).
        unsigned b0 = __ballot_sync(0xffffffffu, cnt & 1);
        unsigned b1 = __ballot_sync(0xffffffffu, (cnt >> 1) & 1);
        unsigned b2 = __ballot_sync(0xffffffffu, (cnt >> 2) & 1);
        unsigned lt = (1u << lane) - 1u;
        int excl = __popc(b0 & lt) + 2 * __popc(b1 & lt) + 4 * __popc(b2 & lt);
        if (lane == 31) swc[wid] = excl + cnt;
        __syncthreads();

        int off = 0, total = 0;
        #pragma unroll
        for (int w = 0; w < NT / 32; w++) {
            int c = swc[w];
            if (w < wid) off += c;
            total += c;
        }
        const int slot0 = off + excl;

        // ---- Capacity-batched compaction + eval (1 batch in practice).
        for (int done = 0; done < total; done += CAP) {
            const int btot = min(total - done, CAP);

            {
                int slot = slot0;
                unsigned m = hm;
                while (m) {
                    int k = __ffs(m) - 1;
                    m &= m - 1;
                    int rel = slot - done;
                    if (rel >= 0 && rel < CAP) {
                        int i = ib + k;
                        s0[rel] = g_p0[i];
                        s1[rel] = g_p1[i];
                    }
                    slot++;
                }
            }
            __syncthreads();

            // ---- Eval: contiguous list, branch-free, dual streams.
            int j = 0;
            for (; j + 1 < btot; j += 2) {
                float4 a0 = s0[j],     b0v = s1[j];
                float4 a1 = s0[j + 1], b1v = s1[j + 1];

                float dx0 = x - a0.x, dy0 = y - a0.y;
                float t0  = fmaf(a0.w, dy0, a0.z * dx0);
                float q0  = fmaf(t0, dx0, (b0v.x * dy0) * dy0);

                float dx1 = x - a1.x, dy1 = y - a1.y;
                float t1  = fmaf(a1.w, dy1, a1.z * dx1);
                float q1  = fmaf(t1, dx1, (b1v.x * dy1) * dy1);

                float w0 = ex2(q0);
                float w1 = ex2(q1);
                w0 = (q0 >= cth) ? w0 : 0.0f;
                w1 = (q1 >= cth) ? w1 : 0.0f;

                ar0 = fmaf(w0, b0v.y, ar0);
                ag0 = fmaf(w0, b0v.z, ag0);
                ab0 = fmaf(w0, b0v.w, ab0);
                ar1 = fmaf(w1, b1v.y, ar1);
                ag1 = fmaf(w1, b1v.z, ag1);
                ab1 = fmaf(w1, b1v.w, ab1);
            }
            if (j < btot) {
                float4 a0 = s0[j], b0v = s1[j];
                float dx0 = x - a0.x, dy0 = y - a0.y;
                float t0  = fmaf(a0.w, dy0, a0.z * dx0);
                float q0  = fmaf(t0, dx0, (b0v.x * dy0) * dy0);
                float w0 = ex2(q0);
                w0 = (q0 >= cth) ? w0 : 0.0f;
                ar0 = fmaf(w0, b0v.y, ar0);
                ag0 = fmaf(w0, b0v.z, ag0);
                ab0 = fmaf(w0, b0v.w, ab0);
            }
            __syncthreads();
        }
    }

    // ---- Composite this segment's partial into out (REDG, no return).
    if (px < W && py < H) {
        int o = (py * W + px) * 3;
        atomicAdd(&out[o + 0], ar0 + ar1);
        atomicAdd(&out[o + 1], ag0 + ag1);
        atomicAdd(&out[o + 2], ab0 + ab1);
    }
}

extern "C" void kernel_launch(void* const* d_in, const int* in_sizes, int n_in,
                              void* d_out, int out_size) {
    const float* opacity = (const float*)d_in[0];
    const float* means   = (const float*)d_in[1];
    const float* stds    = (const float*)d_in[2];
    const float* rhos    = (const float*)d_in[3];
    const float* colors  = (const float*)d_in[4];
    const int*   scale_p = (const int*)d_in[7];
    const int*   ratio_p = (const int*)d_in[8];

    int N = in_sizes[0];
    if (N > MAXN) N = MAXN;

    int hw = out_size / 3;
    int W = (int)lrint(sqrt((double)hw));
    while (W > 1 && (hw % W) != 0) W--;
    int H = hw / W;

    float* out = (float*)d_out;

    // Zero the output (async memset is graph-capturable).
    cudaMemsetAsync(d_out, 0, (size_t)out_size * sizeof(float));

    gr_prep<<<(N + 255) / 256, 256>>>(opacity, means, stds, rhos, colors,
                                      scale_p, ratio_p, N);

    dim3 grid((W + TILE_W - 1) / TILE_W, (H + TILE_H - 1) / TILE_H, NSEG);
    gr_raster<<<grid, NT>>>(ratio_p, out, N, W, H);
}

// round 16
// speedup vs baseline: 1.1781x; 1.1781x over previous
#include <cuda_runtime.h>
#include <math.h>

// ---------------------------------------------------------------------------
// GaussianRasterizer — prepass + single raster kernel.
//   gr_prep  : per Gaussian: bbox vector {mx,my,ex,ey} (tile half folded) +
//              eval-ready {mx,my,qa,qb2}/{qc, o*c} with -0.5*log2e folded
//              (weight = 2^q).
//   gr_raster: one CTA per 16x16 tile, 768 threads = 6 independent
//              128-thread groups over disjoint N-ranges (named barriers).
//              Each thread owns TWO pixels (y and y+8, same x) sharing the
//              dx-dependent terms. Cull = 1 LDG.128 + compares; compaction
//              = float4 copy; branch-free eval. Fixed-order group combine
//              => bit-deterministic.
// ---------------------------------------------------------------------------

#define TILE_W 16
#define TILE_H 16
#define NT 768
#define NG 6
#define GSZ 128
#define CPT 3
#define GCHUNK (GSZ * CPT)      // 384 >= N/6 for N=2048 => single chunk
#define CAP 160                 // survivor batch capacity per group
#define GW (GSZ / 32)
#define MAXN 8192

__device__ float4 g_bb[MAXN];   // {mx, my, ex, ey} (ex,ey include tile half)
__device__ float4 g_p0[MAXN];   // {mx, my, qa, qb2}
__device__ float4 g_p1[MAXN];   // {qc, o*cr, o*cg, o*cb}

__device__ __forceinline__ float scalar_as_float(const int* p) {
    int v = *p;
    if (v >= 0 && v <= 1000000) return (float)v;
    return __int_as_float(v);
}

__device__ __forceinline__ float ex2(float q) {
    float r;
    asm("ex2.approx.ftz.f32 %0, %1;" : "=f"(r) : "f"(q));
    return r;
}

__device__ __forceinline__ void bar_group(int id) {
    asm volatile("bar.sync %0, %1;" :: "r"(id), "n"(GSZ) : "memory");
}

__global__ __launch_bounds__(256)
void gr_prep(const float* __restrict__ opacity,
             const float* __restrict__ means,
             const float* __restrict__ stds,
             const float* __restrict__ rhos,
             const float* __restrict__ colors,
             const int*   __restrict__ scale_p,
             const int*   __restrict__ ratio_p,
             int N) {
    const int i = blockIdx.x * blockDim.x + threadIdx.x;
    if (i >= N) return;

    const float s    = scalar_as_float(scale_p);
    const float r    = scalar_as_float(ratio_p);
    const float rs   = r * s;
    const float HL2E = -0.5f * 1.44269504088896340736f;   // -0.5*log2(e)

    float2 mn = ((const float2*)means)[i];
    float2 st = ((const float2*)stds)[i];
    float rho = rhos[i];
    float o   = opacity[i];
    float c0  = colors[3 * i + 0];
    float c1  = colors[3 * i + 1];
    float c2  = colors[3 * i + 2];

    float sx = st.x * s;
    float sy = st.y * s;
    float om = 1.0f - rho * rho;
    float qa  = __fdividef(HL2E,               sx * sx * om);
    float qc  = __fdividef(HL2E,               sy * sy * om);
    float qb2 = __fdividef(-2.0f * HL2E * rho, sx * sy * om);

    g_bb[i] = make_float4(mn.x, mn.y,
                          fmaf(rs, st.x, (TILE_W - 1) * 0.5f),
                          fmaf(rs, st.y, (TILE_H - 1) * 0.5f));
    g_p0[i] = make_float4(mn.x, mn.y, qa, qb2);
    g_p1[i] = make_float4(qc, o * c0, o * c1, o * c2);
}

__global__ __launch_bounds__(NT, 2)
void gr_raster(const int* __restrict__ ratio_p,
               float* __restrict__ out, int N, int W, int H) {
    __shared__ float4 s0[NG][CAP];
    __shared__ float4 s1[NG][CAP];
    __shared__ int    swc[NG][GW];
    __shared__ float  sacc[NG - 1][GSZ][6];   // 2 px x RGB per thread

    const int tid   = threadIdx.x;
    const int lane  = tid & 31;
    const int g     = tid / GSZ;          // group 0..5
    const int htid  = tid - g * GSZ;      // 0..127 within group
    const int gwid  = htid >> 5;
    const int barid = g + 1;

    // Two pixels per thread: (px, py) and (px, py+8).
    const int px  = blockIdx.x * TILE_W + (htid & (TILE_W - 1));
    const int py0 = blockIdx.y * TILE_H + (htid >> 4);       // rows 0..7
    const int py1 = py0 + 8;                                  // rows 8..15
    const float x  = (float)px + 0.5f;
    const float y0 = (float)py0 + 0.5f;

    const float tcx = (float)(blockIdx.x * TILE_W) + 0.5f + (TILE_W - 1) * 0.5f;
    const float tcy = (float)(blockIdx.y * TILE_H) + 0.5f + (TILE_H - 1) * 0.5f;

    const float r    = scalar_as_float(ratio_p);
    const float HL2E = -0.5f * 1.44269504088896340736f;
    const float cth  = HL2E * r * r;      // pass when folded q >= cth

    const int N6  = (N + NG - 1) / NG;
    const int beg = g * N6;
    const int end = min(N, beg + N6);

    float ar0 = 0.f, ag0 = 0.f, ab0 = 0.f;   // pixel (x, y0)
    float ar1 = 0.f, ag1 = 0.f, ab1 = 0.f;   // pixel (x, y0+8)

    for (int base = beg; base < end; base += GCHUNK) {
        // ---- Cull: CPT candidates per thread, 1 LDG.128 each.
        const int ib = base + htid * CPT;
        unsigned hm = 0;
        #pragma unroll
        for (int k = 0; k < CPT; k++) {
            int i = ib + k;
            if (i < end) {
                float4 bb = g_bb[i];
                bool hit = (fabsf(bb.x - tcx) <= bb.z) &
                           (fabsf(bb.y - tcy) <= bb.w);
                if (hit) hm |= (1u << k);
            }
        }
        int cnt = __popc(hm);

        // ---- 2-ballot prefix scan (cnt in 0..3).
        unsigned b0 = __ballot_sync(0xffffffffu, cnt & 1);
        unsigned b1 = __ballot_sync(0xffffffffu, (cnt >> 1) & 1);
        unsigned lt = (1u << lane) - 1u;
        int excl = __popc(b0 & lt) + 2 * __popc(b1 & lt);
        if (lane == 31) swc[g][gwid] = excl + cnt;
        bar_group(barid);

        int off = 0, total = 0;
        #pragma unroll
        for (int w = 0; w < GW; w++) {
            int c = swc[g][w];
            if (w < gwid) off += c;
            total += c;
        }
        const int slot0 = off + excl;

        // ---- Capacity-batched compaction + eval (1 batch in practice).
        for (int done = 0; done < total; done += CAP) {
            const int btot = min(total - done, CAP);

            {
                int slot = slot0;
                unsigned m = hm;
                while (m) {
                    int k = __ffs(m) - 1;
                    m &= m - 1;
                    int rel = slot - done;
                    if (rel >= 0 && rel < CAP) {
                        int i = ib + k;
                        s0[g][rel] = g_p0[i];
                        s1[g][rel] = g_p1[i];
                    }
                    slot++;
                }
            }
            bar_group(barid);              // survivor batch ready

            // ---- Eval: 2 pixels per gaussian, shared dx terms.
            #pragma unroll 2
            for (int j = 0; j < btot; j++) {
                float4 a = s0[g][j], b = s1[g][j];

                float dx  = x  - a.x;
                float dy0 = y0 - a.y;
                float dy1 = dy0 + 8.0f;

                float u    = a.z * dx;            // qa*dx
                float v    = a.w * dx;            // qb2*dx
                float base_ = u * dx;             // qa*dx^2

                float q0 = fmaf(dy0, fmaf(b.x, dy0, v), base_);
                float q1 = fmaf(dy1, fmaf(b.x, dy1, v), base_);

                float w0 = ex2(q0);
                float w1 = ex2(q1);
                w0 = (q0 >= cth) ? w0 : 0.0f;
                w1 = (q1 >= cth) ? w1 : 0.0f;

                ar0 = fmaf(w0, b.y, ar0);
                ag0 = fmaf(w0, b.z, ag0);
                ab0 = fmaf(w0, b.w, ab0);
                ar1 = fmaf(w1, b.y, ar1);
                ag1 = fmaf(w1, b.z, ag1);
                ab1 = fmaf(w1, b.w, ab1);
            }
            bar_group(barid);              // batch consumed
        }
    }

    // ---- Deterministic combine: groups 1..5 publish; group 0 sums in order.
    if (g) {
        sacc[g - 1][htid][0] = ar0;
        sacc[g - 1][htid][1] = ag0;
        sacc[g - 1][htid][2] = ab0;
        sacc[g - 1][htid][3] = ar1;
        sacc[g - 1][htid][4] = ag1;
        sacc[g - 1][htid][5] = ab1;
    }
    __syncthreads();
    if (g == 0) {
        float sr0 = ar0, sg0 = ag0, sb0 = ab0;
        float sr1 = ar1, sg1 = ag1, sb1 = ab1;
        #pragma unroll
        for (int q = 0; q < NG - 1; q++) {
            sr0 += sacc[q][htid][0];
            sg0 += sacc[q][htid][1];
            sb0 += sacc[q][htid][2];
            sr1 += sacc[q][htid][3];
            sg1 += sacc[q][htid][4];
            sb1 += sacc[q][htid][5];
        }
        if (px < W && py0 < H) {
            int o = (py0 * W + px) * 3;
            out[o + 0] = sr0;
            out[o + 1] = sg0;
            out[o + 2] = sb0;
        }
        if (px < W && py1 < H) {
            int o = (py1 * W + px) * 3;
            out[o + 0] = sr1;
            out[o + 1] = sg1;
            out[o + 2] = sb1;
        }
    }
}

extern "C" void kernel_launch(void* const* d_in, const int* in_sizes, int n_in,
                              void* d_out, int out_size) {
    const float* opacity = (const float*)d_in[0];
    const float* means   = (const float*)d_in[1];
    const float* stds    = (const float*)d_in[2];
    const float* rhos    = (const float*)d_in[3];
    const float* colors  = (const float*)d_in[4];
    const int*   scale_p = (const int*)d_in[7];
    const int*   ratio_p = (const int*)d_in[8];

    int N = in_sizes[0];
    if (N > MAXN) N = MAXN;

    int hw = out_size / 3;
    int W = (int)lrint(sqrt((double)hw));
    while (W > 1 && (hw % W) != 0) W--;
    int H = hw / W;

    float* out = (float*)d_out;

    gr_prep<<<(N + 255) / 256, 256>>>(opacity, means, stds, rhos, colors,
                                      scale_p, ratio_p, N);

    dim3 grid((W + TILE_W - 1) / TILE_W, (H + TILE_H - 1) / TILE_H);
    gr_raster<<<grid, NT>>>(ratio_p, out, N, W, H);
}